// round 17
// baseline (speedup 1.0000x reference)
#include <cuda_runtime.h>
#include <cstdint>

#define T_STEPS 32
#define BATCH   8
#define NT      256
#define CIN_    1024
#define DCH     512
#define KC      64
#define PIX     196

typedef unsigned long long ull;

// ---------------- scratch (device globals; no allocations) ----------------
__device__ float g_xr[NT * DCH * PIX];       // (n, d, p)
__device__ float g_wxb[NT * KC * PIX];       // (n, k, p)
__device__ float g_fwd[NT * KC * PIX];
__device__ float g_bwd[NT * KC * PIX];
__device__ float g_assign[NT * KC * PIX];
__device__ float g_asum[NT * KC];
__device__ float g_vlad[BATCH * KC * DCH];

static __device__ __forceinline__ float sigf(float v) { return 1.0f / (1.0f + expf(-v)); }

// packed fp32x2 helpers
static __device__ __forceinline__ ull pack2(float v) {
    ull r;
    unsigned u = __float_as_uint(v);
    asm("mov.b64 %0, {%1, %1};" : "=l"(r) : "r"(u));
    return r;
}
static __device__ __forceinline__ void ffma2(ull& d, ull a, ull b) {
    asm volatile("fma.rn.f32x2 %0, %1, %2, %0;" : "+l"(d) : "l"(a), "l"(b));
}
static __device__ __forceinline__ float lo32(ull u) { return __uint_as_float((unsigned)u); }
static __device__ __forceinline__ float hi32(ull u) { return __uint_as_float((unsigned)(u >> 32)); }

__device__ __forceinline__ uint32_t smem_to_u32(const void* p) {
    uint32_t a;
    asm("{ .reg .u64 t; cvta.to.shared.u64 t, %1; cvt.u32.u64 %0, t; }" : "=r"(a) : "l"(p));
    return a;
}
__device__ __forceinline__ uint32_t mapa_u32(uint32_t addr, uint32_t rank) {
    uint32_t r;
    asm("mapa.shared::cluster.u32 %0, %1, %2;" : "=r"(r) : "r"(addr), "r"(rank));
    return r;
}
__device__ __forceinline__ void st_dsmem64(uint32_t addr, ull v) {
    asm volatile("st.shared::cluster.b64 [%0], %1;" :: "r"(addr), "l"(v) : "memory");
}
#define CLUSTER_SYNC() do { \
    asm volatile("barrier.cluster.arrive.aligned;" ::: "memory"); \
    asm volatile("barrier.cluster.wait.aligned;" ::: "memory"); \
} while (0)

// ---------------- init: zero vlad accumulator ----------------
__global__ void init_kernel()
{
    int i = blockIdx.x * 256 + threadIdx.x;
    if (i < BATCH * KC * DCH) g_vlad[i] = 0.0f;
}

// ---------------- 1x1 conv as double-buffered tiled SGEMM (f32x2 FMAs) ----------------
// out[(n*OC + d)*196 + p] = bias[d] + sum_c W[d][c] * X[(n*CIN + c)*196 + p]
template<int BM, int TM, int CIN, int OC>
__global__ void __launch_bounds__(256)
conv1x1_db(const float* __restrict__ X, const float* __restrict__ W,
           const float* __restrict__ bias, float* __restrict__ out)
{
    constexpr int BK = 16, BN = 128, TN = 8;
    constexpr int AL4 = (BM * BK) / (4 * 256);
    __shared__ __align__(16) float As[2][BK][BM];
    __shared__ __align__(16) float Bs[2][BK][BN];
    __shared__ int cbase[BN], obase[BN];

    const int tid = threadIdx.x;
    if (tid < BN) {
        int jg = blockIdx.x * BN + tid;
        int n = jg / PIX, p = jg - n * PIX;
        cbase[tid] = n * CIN * PIX + p;
        obase[tid] = n * OC * PIX + p;
    }
    __syncthreads();

    const int m0 = blockIdx.y * BM;
    const int tx = tid & 15, ty = tid >> 4;
    const int bj = tid & 127, bk = tid >> 7;
    const int cb = cbase[bj];

    float4 areg[AL4];
    float  breg[8];

    auto loadA = [&](int k0) {
#pragma unroll
        for (int i = 0; i < AL4; i++) {
            int idx = tid + i * 256;
            int r = idx >> 2, c4 = idx & 3;
            areg[i] = *(const float4*)&W[(m0 + r) * CIN + k0 + c4 * 4];
        }
    };
    auto loadB = [&](int k0) {
#pragma unroll
        for (int i = 0; i < 8; i++) breg[i] = X[cb + (k0 + bk * 8 + i) * PIX];
    };
    auto storeA = [&](int buf) {
#pragma unroll
        for (int i = 0; i < AL4; i++) {
            int idx = tid + i * 256;
            int r = idx >> 2, c4 = idx & 3;
            As[buf][c4 * 4 + 0][r] = areg[i].x;
            As[buf][c4 * 4 + 1][r] = areg[i].y;
            As[buf][c4 * 4 + 2][r] = areg[i].z;
            As[buf][c4 * 4 + 3][r] = areg[i].w;
        }
    };
    auto storeB = [&](int buf) {
#pragma unroll
        for (int i = 0; i < 8; i++) Bs[buf][bk * 8 + i][bj] = breg[i];
    };

    ull acc2[TM / 2][TN];
#pragma unroll
    for (int i = 0; i < TM / 2; i++)
#pragma unroll
        for (int j = 0; j < TN; j++) acc2[i][j] = 0ull;

    loadA(0); loadB(0);
    storeA(0); storeB(0);
    __syncthreads();

    int buf = 0;
    for (int k0 = 0; k0 < CIN; k0 += BK) {
        const bool more = (k0 + BK) < CIN;
        if (more) { loadA(k0 + BK); loadB(k0 + BK); }
#pragma unroll
        for (int kk = 0; kk < BK; kk++) {
            ull a2[TM / 2];
#pragma unroll
            for (int i = 0; i < TM / 2; i += 2) {
                ulonglong2 av = *(const ulonglong2*)&As[buf][kk][ty * TM + i * 2];
                a2[i] = av.x; a2[i + 1] = av.y;
            }
            float4 b0 = *(const float4*)&Bs[buf][kk][tx * TN];
            float4 b1 = *(const float4*)&Bs[buf][kk][tx * TN + 4];
            ull bb[8];
            bb[0] = pack2(b0.x); bb[1] = pack2(b0.y); bb[2] = pack2(b0.z); bb[3] = pack2(b0.w);
            bb[4] = pack2(b1.x); bb[5] = pack2(b1.y); bb[6] = pack2(b1.z); bb[7] = pack2(b1.w);
#pragma unroll
            for (int i = 0; i < TM / 2; i++)
#pragma unroll
                for (int j = 0; j < TN; j++) ffma2(acc2[i][j], a2[i], bb[j]);
        }
        if (more) {
            storeA(buf ^ 1); storeB(buf ^ 1);
            __syncthreads();
            buf ^= 1;
        }
    }

#pragma unroll
    for (int i = 0; i < TM / 2; i++) {
        int d0 = m0 + ty * TM + 2 * i;
        float bv0 = bias[d0], bv1 = bias[d0 + 1];
#pragma unroll
        for (int j = 0; j < TN; j++) {
            ull u = acc2[i][j];
            int o = obase[tx * TN + j];
            out[o + d0 * PIX]       = lo32(u) + bv0;
            out[o + (d0 + 1) * PIX] = hi32(u) + bv1;
        }
    }
}

// ---------------- persistent bidirectional GRU: 8-CTA clusters, DSMEM exchange ----------------
// 16 clusters = 16 (dir,b) groups; rank kg owns 8 ko channels. Per phase, each CTA
// broadcasts its ko-slab into ALL 8 CTAs' hs images via mapa + st.shared::cluster.
// No global h state, no global barriers, no restage loops.
#define GRU_THREADS 448
#define HS_STRIDE   288                    // 16 * 18
#define HS_FLOATS   (64 * HS_STRIDE)       // 18432
#define WS_FLOATS   4608
#define PQ_FLOATS   1568
#define CSTG_FLOATS (8 * 14 * 16)          // 1792, shifted-row layout [ko_l][14][16]
#define GRU_SMEM_FLOATS (HS_FLOATS + 3 * WS_FLOATS + 6 * PQ_FLOATS + CSTG_FLOATS)

__global__ void __launch_bounds__(GRU_THREADS, 1) __cluster_dims__(8, 1, 1)
gru_persistent(const float* __restrict__ Uz, const float* __restrict__ Ur,
               const float* __restrict__ Uh)
{
    extern __shared__ float sm[];
    float* hs   = sm;                      // 64 channels, 16x18 padded
    float* wz   = sm + HS_FLOATS;
    float* wr   = wz + WS_FLOATS;
    float* wh   = wr + WS_FLOATS;
    float* pz   = wh + WS_FLOATS;          // 3*1568 partials (z / hcand)
    float* pr   = pz + 3 * PQ_FLOATS;      // 3*1568 partials (r)
    float* cstg = pr + 3 * PQ_FLOATS;      // compact outgoing slab

    const int blk = blockIdx.x;
    const int grp = blk >> 3;              // dir*8 + b
    const int kg  = blk & 7;               // == cluster rank
    const int dir = grp >> 3;
    const int b   = grp & 7;
    const int tid = threadIdx.x;

    const int ko0 = kg * 8;
    for (int i = tid; i < WS_FLOATS; i += GRU_THREADS) {
        wz[i] = Uz[ko0 * 576 + i];
        wr[i] = Ur[ko0 * 576 + i];
        wh[i] = Uh[ko0 * 576 + i];
    }
    for (int i = tid; i < HS_FLOATS; i += GRU_THREADS) hs[i] = 0.0f;
    __syncthreads();

    uint32_t pbase[8];
    {
        uint32_t hu = smem_to_u32(hs);
#pragma unroll
        for (int p = 0; p < 8; p++) pbase[p] = mapa_u32(hu, (uint32_t)p);
    }

    const int q     = tid / 112;           // ci-quarter 0..3
    const int lt    = tid - q * 112;
    const int ko_l  = lt / 14;             // 0..7
    const int row   = lt - ko_l * 14;      // 0..13
    const int ko    = ko0 + ko_l;
    const int ci0   = q * 16;
    const int pidx  = ko_l * PIX + row * 14;

    float* gdst = (dir == 0) ? g_fwd : g_bwd;
    float zreg[14], hold[14];

    // broadcast local cstg slab into all 8 CTAs' hs (incl. own)
    auto scatter = [&]() {
        for (int it = tid; it < 896; it += GRU_THREADS) {
            int kl  = it / 112;
            int rem = it - kl * 112;
            int y = rem >> 3, jx = rem & 7;
            ull v = *(const ull*)(cstg + kl * 224 + y * 16 + jx * 2);
            uint32_t off = (uint32_t)(((ko0 + kl) * HS_STRIDE + (y + 1) * 18 + jx * 2) * 4);
#pragma unroll
            for (int p = 0; p < 8; p++) st_dsmem64(pbase[p] + off, v);
        }
    };

    for (int s = 0; s < T_STEPS; s++) {
        const int t = dir ? (31 - s) : s;
        const int n = b * 32 + t;
        const float* wt = g_wxb + (n * KC + ko) * PIX + row * 14;

        // ---- phase A: z,r convs over this quarter's 16 channels (hs = h) ----
        ull az2[7], ar2[7];
#pragma unroll
        for (int j = 0; j < 7; j++) { az2[j] = 0ull; ar2[j] = 0ull; }
        {
            const float* wzb = wz + ko_l * 576 + ci0 * 9;
            const float* wrb = wr + ko_l * 576 + ci0 * 9;
            const float* hbase = hs + ci0 * HS_STRIDE + row * 18;
#pragma unroll 1
            for (int ci = 0; ci < 16; ci++) {
                const float* hrow = hbase + ci * HS_STRIDE;
                const float* wz9 = wzb + ci * 9;
                const float* wr9 = wrb + ci * 9;
#pragma unroll
                for (int r = 0; r < 3; r++) {
                    ull p[8];
#pragma unroll
                    for (int k = 0; k < 8; k++)
                        p[k] = *(const ull*)(hrow + r * 18 + 2 * k);
                    ull wa0 = pack2(wz9[3 * r + 0]);
                    ull wa1 = pack2(wz9[3 * r + 1]);
                    ull wa2 = pack2(wz9[3 * r + 2]);
                    ull wb0 = pack2(wr9[3 * r + 0]);
                    ull wb1 = pack2(wr9[3 * r + 1]);
                    ull wb2 = pack2(wr9[3 * r + 2]);
#pragma unroll
                    for (int j = 0; j < 7; j++) {
                        ull sft = (p[j] >> 32) | (p[j + 1] << 32);
                        ffma2(az2[j], p[j],     wa0);
                        ffma2(az2[j], sft,      wa1);
                        ffma2(az2[j], p[j + 1], wa2);
                        ffma2(ar2[j], p[j],     wb0);
                        ffma2(ar2[j], sft,      wb1);
                        ffma2(ar2[j], p[j + 1], wb2);
                    }
                }
            }
        }
        if (q > 0) {
            ull* pzq = (ull*)(pz + (q - 1) * PQ_FLOATS + pidx);
            ull* prq = (ull*)(pr + (q - 1) * PQ_FLOATS + pidx);
#pragma unroll
            for (int j = 0; j < 7; j++) { pzq[j] = az2[j]; prq[j] = ar2[j]; }
        }
        __syncthreads();
        if (q == 0) {
            float az[14], ar[14];
#pragma unroll
            for (int j = 0; j < 7; j++) {
                az[2 * j] = lo32(az2[j]); az[2 * j + 1] = hi32(az2[j]);
                ar[2 * j] = lo32(ar2[j]); ar[2 * j + 1] = hi32(ar2[j]);
            }
#pragma unroll
            for (int qq = 0; qq < 3; qq++) {
                const float* pzq = pz + qq * PQ_FLOATS + pidx;
                const float* prq = pr + qq * PQ_FLOATS + pidx;
#pragma unroll
                for (int px = 0; px < 14; px++) { az[px] += pzq[px]; ar[px] += prq[px]; }
            }
            const float* hko = hs + ko * HS_STRIDE + (row + 1) * 18 + 1;
            float* cr = cstg + ko_l * 224 + row * 16;
            cr[0] = 0.0f; cr[15] = 0.0f;
#pragma unroll
            for (int px = 0; px < 14; px++) {
                float w = wt[px];
                float z = sigf(w + az[px]);
                float r = sigf(w + ar[px]);
                float h0 = hko[px];
                zreg[px] = z;
                hold[px] = h0;
                cr[1 + px] = r * h0;
            }
        }
        CLUSTER_SYNC();    // all CTAs done reading hs; cstg ready
        scatter();
        CLUSTER_SYNC();    // hs = r*h image

        // ---- phase B: h-candidate conv (hs = r*h) ----
        ull ah2[7];
#pragma unroll
        for (int j = 0; j < 7; j++) ah2[j] = 0ull;
        {
            const float* whb = wh + ko_l * 576 + ci0 * 9;
            const float* hbase = hs + ci0 * HS_STRIDE + row * 18;
#pragma unroll 1
            for (int ci = 0; ci < 16; ci++) {
                const float* hrow = hbase + ci * HS_STRIDE;
                const float* w9 = whb + ci * 9;
#pragma unroll
                for (int r = 0; r < 3; r++) {
                    ull p[8];
#pragma unroll
                    for (int k = 0; k < 8; k++)
                        p[k] = *(const ull*)(hrow + r * 18 + 2 * k);
                    ull wa0 = pack2(w9[3 * r + 0]);
                    ull wa1 = pack2(w9[3 * r + 1]);
                    ull wa2 = pack2(w9[3 * r + 2]);
#pragma unroll
                    for (int j = 0; j < 7; j++) {
                        ull sft = (p[j] >> 32) | (p[j + 1] << 32);
                        ffma2(ah2[j], p[j],     wa0);
                        ffma2(ah2[j], sft,      wa1);
                        ffma2(ah2[j], p[j + 1], wa2);
                    }
                }
            }
        }
        if (q > 0) {
            ull* pzq = (ull*)(pz + (q - 1) * PQ_FLOATS + pidx);
#pragma unroll
            for (int j = 0; j < 7; j++) pzq[j] = ah2[j];
        }
        __syncthreads();
        if (q == 0) {
            float ah[14];
#pragma unroll
            for (int j = 0; j < 7; j++) {
                ah[2 * j] = lo32(ah2[j]); ah[2 * j + 1] = hi32(ah2[j]);
            }
#pragma unroll
            for (int qq = 0; qq < 3; qq++) {
                const float* pzq = pz + qq * PQ_FLOATS + pidx;
#pragma unroll
                for (int px = 0; px < 14; px++) ah[px] += pzq[px];
            }
            float* fdst = gdst + (n * KC + ko) * PIX + row * 14;
            float* cr = cstg + ko_l * 224 + row * 16;
            cr[0] = 0.0f; cr[15] = 0.0f;
#pragma unroll
            for (int px = 0; px < 14; px++) {
                float hh = tanhf(wt[px] + ah[px]);
                float z  = zreg[px];
                float hn = (1.0f - z) * hh + z * hold[px];
                cr[1 + px] = hn;
                fdst[px] = hn;
            }
        }
        CLUSTER_SYNC();    // all CTAs done reading hs; cstg ready
        scatter();
        CLUSTER_SYNC();    // hs = new h
    }
}

// ---------------- softmax over K per pixel (single exp pass via SMEM) ----------------
// dynamic smem: se[64][224] floats = 57344 B
__global__ void softmax_kernel()
{
    extern __shared__ float se[];
    const int n = blockIdx.x;
    const int p = threadIdx.x;   // 224 threads, 196 active
    const bool act = p < PIX;
    __shared__ float asum_s[KC];
    if (p < KC) asum_s[p] = 0.0f;
    __syncthreads();

    const float* f  = g_fwd + n * KC * PIX + p;
    const float* bd = g_bwd + n * KC * PIX + p;
    float m = -1e30f;
    if (act) {
        for (int k = 0; k < KC; k++) {
            float v = f[k * PIX] + bd[k * PIX];
            se[k * 224 + p] = v;
            m = fmaxf(m, v);
        }
    }
    float ssum = 0.0f;
    if (act) {
        for (int k = 0; k < KC; k++) {
            float e = expf(se[k * 224 + p] - m);
            se[k * 224 + p] = e;
            ssum += e;
        }
    }
    const float inv = act ? (1.0f / ssum) : 0.0f;
    float* A = g_assign + n * KC * PIX + p;
    for (int k = 0; k < KC; k++) {
        float e = act ? se[k * 224 + p] * inv : 0.0f;
        if (act) A[k * PIX] = e;
        float es = e;
#pragma unroll
        for (int off = 16; off; off >>= 1) es += __shfl_down_sync(0xffffffffu, es, off);
        if ((p & 31) == 0) atomicAdd(&asum_s[k], es);
    }
    __syncthreads();
    if (p < KC) g_asum[n * KC + p] = asum_s[p];
}

// ---------------- VLAD einsum: vlad[b,k,d] += sum_{t,p} assign * xr ----------------
__global__ void vlad_gemm_kernel()
{
    __shared__ float As[14][65];
    __shared__ float Bs[14][65];
    const int b = blockIdx.y, d0 = blockIdx.x * 64, ch = blockIdx.z;
    const int tid = threadIdx.x;
    const int tx = tid & 15, ty = tid >> 4;

    float acc[4][4];
#pragma unroll
    for (int i = 0; i < 4; i++)
#pragma unroll
        for (int j = 0; j < 4; j++) acc[i][j] = 0.0f;

    for (int f = 0; f < 4; f++) {
        int n = b * 32 + ch * 4 + f;
        const float* Ap = g_assign + n * KC * PIX;
        const float* Xp = g_xr + (size_t)n * DCH * PIX;
        for (int p0 = 0; p0 < PIX; p0 += 14) {
            for (int i = tid; i < 896; i += 256) {
                int r = i / 14, pp = i - r * 14;
                As[pp][r] = Ap[r * PIX + p0 + pp];
                Bs[pp][r] = Xp[(d0 + r) * PIX + p0 + pp];
            }
            __syncthreads();
#pragma unroll
            for (int pp = 0; pp < 14; pp++) {
                float a[4], x[4];
#pragma unroll
                for (int i = 0; i < 4; i++) a[i] = As[pp][ty * 4 + i];
#pragma unroll
                for (int j = 0; j < 4; j++) x[j] = Bs[pp][tx * 4 + j];
#pragma unroll
                for (int i = 0; i < 4; i++)
#pragma unroll
                    for (int j = 0; j < 4; j++) acc[i][j] += a[i] * x[j];
            }
            __syncthreads();
        }
    }
#pragma unroll
    for (int i = 0; i < 4; i++)
#pragma unroll
        for (int j = 0; j < 4; j++)
            atomicAdd(&g_vlad[(b * KC + ty * 4 + i) * DCH + d0 + tx * 4 + j], acc[i][j]);
}

// ---------------- subtract a-term + intra-row L2 normalize ----------------
__global__ void rownorm_kernel(const float* __restrict__ centers, float* __restrict__ out)
{
    const int k = blockIdx.x, b = blockIdx.y;
    const int tid = threadIdx.x;  // 128
    __shared__ float sred[128];
    __shared__ float s_sh;

    if (tid < 32) {
        float s = g_asum[(b * 32 + tid) * KC + k];
#pragma unroll
        for (int off = 16; off; off >>= 1) s += __shfl_down_sync(0xffffffffu, s, off);
        if (tid == 0) s_sh = s;
    }
    __syncthreads();
    const float s = s_sh;

    float v[4];
    float ssq = 0.0f;
#pragma unroll
    for (int j = 0; j < 4; j++) {
        int d = j * 128 + tid;
        v[j] = g_vlad[(b * KC + k) * DCH + d] - s * centers[k * DCH + d];
        ssq += v[j] * v[j];
    }
    sred[tid] = ssq;
    __syncthreads();
    for (int off = 64; off; off >>= 1) {
        if (tid < off) sred[tid] += sred[tid + off];
        __syncthreads();
    }
    const float scale = 1.0f / fmaxf(sqrtf(sred[0]), 1e-12f);
#pragma unroll
    for (int j = 0; j < 4; j++)
        out[b * KC * DCH + k * DCH + j * 128 + tid] = v[j] * scale;
}

// ---------------- final per-batch L2 normalize ----------------
__global__ void bnorm_kernel(float* __restrict__ out)
{
    const int b = blockIdx.x;
    const int tid = threadIdx.x; // 256
    __shared__ float sred[256];
    float* o = out + b * KC * DCH;
    float ssq = 0.0f;
    for (int i = tid; i < KC * DCH; i += 256) { float v = o[i]; ssq += v * v; }
    sred[tid] = ssq;
    __syncthreads();
    for (int off = 128; off; off >>= 1) {
        if (tid < off) sred[tid] += sred[tid + off];
        __syncthreads();
    }
    const float scale = 1.0f / fmaxf(sqrtf(sred[0]), 1e-12f);
    for (int i = tid; i < KC * DCH; i += 256) o[i] *= scale;
}

// ---------------- host launcher ----------------
extern "C" void kernel_launch(void* const* d_in, const int* in_sizes, int n_in,
                              void* d_out, int out_size)
{
    const float* x       = (const float*)d_in[0];
    const float* redu_w  = (const float*)d_in[1];
    const float* redu_b  = (const float*)d_in[2];
    const float* share_w = (const float*)d_in[3];
    const float* share_b = (const float*)d_in[4];
    const float* U_z     = (const float*)d_in[5];
    const float* U_r     = (const float*)d_in[6];
    const float* U_h     = (const float*)d_in[7];
    const float* centers = (const float*)d_in[8];
    float* out = (float*)d_out;

    const int GRU_SMEM = GRU_SMEM_FLOATS * 4;   // ~173.8 KB
    cudaFuncSetAttribute(gru_persistent, cudaFuncAttributeMaxDynamicSharedMemorySize, GRU_SMEM);
    cudaFuncSetAttribute(softmax_kernel, cudaFuncAttributeMaxDynamicSharedMemorySize, 57344);

    void* xr_p;  cudaGetSymbolAddress(&xr_p,  g_xr);
    void* wxb_p; cudaGetSymbolAddress(&wxb_p, g_wxb);

    init_kernel<<<1024, 256>>>();

    // xr = 1x1 reduce conv + bias : GEMM (512 x 1024) @ (1024 x 50176)
    conv1x1_db<128, 8, CIN_, DCH>
        <<<dim3(50176 / 128, DCH / 128), 256>>>(x, redu_w, redu_b, (float*)xr_p);

    // wxb = 1x1 share conv + bias : GEMM (64 x 512) @ (512 x 50176)
    conv1x1_db<64, 4, DCH, KC>
        <<<dim3(50176 / 128, 1), 256>>>((const float*)xr_p, share_w, share_b, (float*)wxb_p);

    // persistent bidirectional GRU: 16 clusters of 8 CTAs, DSMEM exchange
    gru_persistent<<<128, GRU_THREADS, GRU_SMEM>>>(U_z, U_r, U_h);

    softmax_kernel<<<NT, 224, 57344>>>();
    vlad_gemm_kernel<<<dim3(8, BATCH, 8), 256>>>();
    rownorm_kernel<<<dim3(KC, BATCH), 128>>>(centers, out);
    bnorm_kernel<<<BATCH, 256>>>(out);
}